// round 15
// baseline (speedup 1.0000x reference)
#include <cuda_runtime.h>
#include <cuda_bf16.h>
#include <cuda_fp16.h>
#include <cstdint>

#define Bn 1024
#define Tn 256
#define Cn 384
#define Hn 64

// Q/K/V as fp16, packed 2 cols per uint32: idx = row*32 + col/2.
// Q is pre-scaled by 0.125 (exact, power of two).
__device__ __align__(16) uint32_t g_q16[Bn * Tn * 32];
__device__ __align__(16) uint32_t g_k16[Bn * Tn * 32];
__device__ __align__(16) uint32_t g_v16[Bn * Tn * 32];

// Pre-packed fp16 B fragments for mma.sync.m16n8k16 (row.col)
__device__ __align__(16) uint2 g_bfrag[24 * 24 * 32];

// ---------------------------------------------------------------------------
__device__ __forceinline__ uint32_t smem_u32(const void* p) {
    uint32_t a;
    asm("{ .reg .u64 t; cvta.to.shared.u64 t, %1; cvt.u32.u64 %0, t; }" : "=r"(a) : "l"(p));
    return a;
}
__device__ __forceinline__ uint32_t pack_fp16(float a, float b) {
    uint32_t lo = __half_as_ushort(__float2half_rn(a));
    uint32_t hi = __half_as_ushort(__float2half_rn(b));
    return lo | (hi << 16);
}
__device__ __forceinline__ void mma_fp16(float* c, const uint32_t* a,
                                         uint32_t b0, uint32_t b1) {
    asm volatile(
        "mma.sync.aligned.m16n8k16.row.col.f32.f16.f16.f32 "
        "{%0,%1,%2,%3}, {%4,%5,%6,%7}, {%8,%9}, {%0,%1,%2,%3};"
        : "+f"(c[0]), "+f"(c[1]), "+f"(c[2]), "+f"(c[3])
        : "r"(a[0]), "r"(a[1]), "r"(a[2]), "r"(a[3]), "r"(b0), "r"(b1));
}
__device__ __forceinline__ void ldmatrix_x4(uint32_t* r, uint32_t addr) {
    asm volatile(
        "ldmatrix.sync.aligned.m8n8.x4.shared.b16 {%0,%1,%2,%3}, [%4];"
        : "=r"(r[0]), "=r"(r[1]), "=r"(r[2]), "=r"(r[3]) : "r"(addr));
}
__device__ __forceinline__ void ldmatrix_x4_trans(uint32_t* r, uint32_t addr) {
    asm volatile(
        "ldmatrix.sync.aligned.m8n8.x4.trans.shared.b16 {%0,%1,%2,%3}, [%4];"
        : "=r"(r[0]), "=r"(r[1]), "=r"(r[2]), "=r"(r[3]) : "r"(addr));
}
#define CP_ASYNC16(dst, src) \
    asm volatile("cp.async.cg.shared.global [%0], [%1], 16;" :: "r"(dst), "l"(src))
#define CP_COMMIT() asm volatile("cp.async.commit_group;" ::: "memory")
#define CP_WAIT(n)  asm volatile("cp.async.wait_group %0;" :: "n"(n) : "memory")

// ---------------------------------------------------------------------------
// Weight prep: fp16 W fragments in mma.sync register layout.
// ---------------------------------------------------------------------------
__global__ void prep_w_kernel(const float* __restrict__ Wk,
                              const float* __restrict__ Wq,
                              const float* __restrict__ Wv) {
    int idx = blockIdx.x * 256 + threadIdx.x;
    if (idx >= 24 * 24 * 32) return;
    int lane = idx & 31;
    int nt = (idx >> 5) % 24;
    int kt = (idx >> 5) / 24;

    int n = nt * 8 + (lane >> 2);
    int k0 = kt * 16 + (lane & 3) * 2;
    const float* W = (n < 64) ? Wq : (n < 128) ? Wk : Wv;
    int nc = n & 63;

    uint2 f;
    f.x = pack_fp16(W[(k0 + 0) * Hn + nc], W[(k0 + 1) * Hn + nc]);
    f.y = pack_fp16(W[(k0 + 8) * Hn + nc], W[(k0 + 9) * Hn + nc]);
    g_bfrag[idx] = f;
}

// ---------------------------------------------------------------------------
// Projection GEMM: single-product fp16, one sync per k-chunk.
// Block tile M=128, N=192; 8 warps (4 x M, 2 x N). 12 k-chunks of 32.
// ---------------------------------------------------------------------------
#define SB_OFF_U8 20480
#define PROJ_SMEM (20480 + 2 * 12288)

__global__ __launch_bounds__(256) void proj_mma_kernel(const float* __restrict__ x) {
    extern __shared__ __align__(16) char psm[];
    uint32_t* sA = (uint32_t*)psm;                 // [st*2560 + row*20 + col]
    uint2*    sB = (uint2*)(psm + SB_OFF_U8);      // [st*1536 + frag]

    const int tid = threadIdx.x;
    const int wid = tid >> 5;
    const int lane = tid & 31;
    const int row0 = blockIdx.x * 128;

    const int wm = (wid & 3) * 32;
    const int nw = wid >> 2;

    const int xr = tid >> 1;
    const int xc = (tid & 1) * 16;
    const float* xrow = x + (size_t)(row0 + xr) * Cn + xc;
    const char* gB = (const char*)g_bfrag;

#pragma unroll
    for (int j = 0; j < 3; ++j)
        CP_ASYNC16(smem_u32((char*)sB + (tid + j * 256) * 16),
                   gB + (tid + j * 256) * 16);
    CP_COMMIT();

    float4 v[4];
#pragma unroll
    for (int j = 0; j < 4; ++j) v[j] = __ldg((const float4*)xrow + j);
    {
        const int base = xr * 20 + xc / 2;
#pragma unroll
        for (int j = 0; j < 4; ++j) {
            sA[base + 2 * j + 0] = pack_fp16(v[j].x, v[j].y);
            sA[base + 2 * j + 1] = pack_fp16(v[j].z, v[j].w);
        }
    }

    float acc[2][12][4];
#pragma unroll
    for (int mt = 0; mt < 2; ++mt)
#pragma unroll
        for (int nt = 0; nt < 12; ++nt)
#pragma unroll
            for (int e = 0; e < 4; ++e) acc[mt][nt][e] = 0.f;

    const int lrow = lane & 15;
    const int lk8 = (lane >> 4) * 8;

    for (int c = 0; c < 12; ++c) {
        const int st = c & 1;

        if (c < 11) {
#pragma unroll
            for (int j = 0; j < 3; ++j)
                CP_ASYNC16(smem_u32((char*)sB + (st ^ 1) * 12288 + (tid + j * 256) * 16),
                           gB + (c + 1) * 12288 + (tid + j * 256) * 16);
            CP_COMMIT();
            const float* nx = xrow + (c + 1) * 32;
#pragma unroll
            for (int j = 0; j < 4; ++j) v[j] = __ldg((const float4*)nx + j);
        }
        if (c < 11) { CP_WAIT(1); } else { CP_WAIT(0); }
        __syncthreads();   // B_c arrived + A_c visible; prior readers of st done

        const uint32_t aBase = smem_u32(&sA[st * 2560]);

#pragma unroll
        for (int kt = 0; kt < 2; ++kt) {
            uint32_t af[2][4];
#pragma unroll
            for (int mt = 0; mt < 2; ++mt) {
                uint32_t off = (uint32_t)((wm + mt * 16 + lrow) * 80 +
                                          (kt * 16 + lk8) * 2);
                ldmatrix_x4(af[mt], aBase + off);
            }
            const uint2* bp = sB + (st * 1536 + ((kt * 24 + nw * 12) * 32 + lane));
#pragma unroll
            for (int nt = 0; nt < 12; ++nt) {
                uint2 bf = bp[nt * 32];
#pragma unroll
                for (int mt = 0; mt < 2; ++mt)
                    mma_fp16(acc[mt][nt], af[mt], bf.x, bf.y);
            }
        }

        // Restage A for chunk c+1 into the other stage. No barrier needed:
        // chunk c-1's readers of sA[st^1] completed before this chunk's sync,
        // and chunk c+1's readers are guarded by its own sync.
        if (c < 11) {
            const int base = (st ^ 1) * 2560 + xr * 20 + xc / 2;
#pragma unroll
            for (int j = 0; j < 4; ++j) {
                sA[base + 2 * j + 0] = pack_fp16(v[j].x, v[j].y);
                sA[base + 2 * j + 1] = pack_fp16(v[j].z, v[j].w);
            }
        }
    }

    // --- Epilogue: Q (pre-scaled), K, V all fp16 packed ---
#pragma unroll
    for (int mt = 0; mt < 2; ++mt) {
#pragma unroll
        for (int nt = 0; nt < 12; ++nt) {
            int n = nw * 96 + nt * 8 + (lane & 3) * 2;
            size_t r0g = (size_t)(row0 + wm + mt * 16 + (lane >> 2));
            float v0 = acc[mt][nt][0], v1 = acc[mt][nt][1];
            float v2 = acc[mt][nt][2], v3 = acc[mt][nt][3];
            uint32_t* dst;
            float sc;
            if (n < 64)      { dst = g_q16; sc = 0.125f; }
            else if (n < 128){ dst = g_k16; sc = 1.0f; }
            else             { dst = g_v16; sc = 1.0f; }
            int col2 = (n & 63) >> 1;
            dst[r0g * 32 + col2]       = pack_fp16(v0 * sc, v1 * sc);
            dst[(r0g + 8) * 32 + col2] = pack_fp16(v2 * sc, v3 * sc);
        }
    }
}

// ---------------------------------------------------------------------------
// Flash-attention: single-product fp16 throughout. Q pre-rounded fp16 from
// proj; P rounded to fp16. 128 q-rows per block (8 warps x 16 rows), K/V
// staged via cp.async, double-buffered.
// ---------------------------------------------------------------------------
#define ARR_B   9216
#define STAGE_B (2 * ARR_B)
#define ATTN_SMEM (2 * STAGE_B)

__device__ __forceinline__ void stage_tile(uint32_t dst, int b, int kt, int tid) {
    size_t base_byte = (((size_t)b * Tn + kt * 64) * 64) * 2;
    const char* pk = (const char*)g_k16 + base_byte;
    const char* pv = (const char*)g_v16 + base_byte;
#pragma unroll
    for (int i = 0; i < 2; ++i) {
        int g = tid * 2 + i;
        uint32_t doff = (uint32_t)((g >> 3) * 144 + (g & 7) * 16);
        CP_ASYNC16(dst + 0 * ARR_B + doff, pk + g * 16);
        CP_ASYNC16(dst + 1 * ARR_B + doff, pv + g * 16);
    }
}

__global__ __launch_bounds__(256) void attn_mma_kernel(float* __restrict__ out)
{
    extern __shared__ __align__(16) char tsm[];
    const uint32_t smb = smem_u32(tsm);

    const int tid = threadIdx.x;
    const int wid = tid >> 5;
    const int lane = tid & 31;
    const int qt = blockIdx.x;
    const int b = blockIdx.y;
    const int qb = wid * 16;
    const int qbg = qt * 128 + qb;
    const int kmax = qt * 2 + 1;
    const int ri = lane & 7;
    const int tq = lane >> 3;
    const int r_lo = lane >> 2;
    const int cb = (lane & 3) * 2;

    stage_tile(smb, b, 0, tid);            CP_COMMIT();
    stage_tile(smb + STAGE_B, b, 1, tid);  CP_COMMIT();

    // --- Q A-fragments: direct LDG of pre-scaled, pre-rounded fp16 pairs ---
    uint32_t qf[4][4];
    {
        const uint32_t* qp = g_q16 + ((size_t)b * Tn + qbg + r_lo) * 32;
#pragma unroll
        for (int k16 = 0; k16 < 4; ++k16) {
            int c2 = (k16 * 16 + cb) >> 1;
            qf[k16][0] = __ldg(qp + c2);
            qf[k16][1] = __ldg(qp + 8 * 32 + c2);
            qf[k16][2] = __ldg(qp + c2 + 4);
            qf[k16][3] = __ldg(qp + 8 * 32 + c2 + 4);
        }
    }

    float o[8][4];
#pragma unroll
    for (int nt = 0; nt < 8; ++nt)
#pragma unroll
        for (int e = 0; e < 4; ++e) o[nt][e] = 0.f;
    float m0 = -1e30f, m1 = -1e30f, l0 = 0.f, l1 = 0.f;

    for (int kt = 0; kt <= kmax; ++kt) {
        CP_WAIT(1);
        __syncthreads();

        const uint32_t stb = smb + (kt & 1) * STAGE_B;
        const bool active = (kt * 64) <= (qbg + 15);

        if (active) {
            // --- S = Q K^T : single-product fp16 ---
            float s[8][4];
#pragma unroll
            for (int nt = 0; nt < 8; ++nt)
#pragma unroll
                for (int e = 0; e < 4; ++e) s[nt][e] = 0.f;

#pragma unroll
            for (int k16 = 0; k16 < 4; ++k16) {
#pragma unroll
                for (int np = 0; np < 4; ++np) {
                    int krow = np * 16 + (tq >> 1) * 8 + ri;
                    int h = k16 * 16 + (tq & 1) * 8;
                    uint32_t kh[4];
                    ldmatrix_x4(kh, stb + 0 * ARR_B + krow * 144 + h * 2);
                    mma_fp16(s[2 * np],     qf[k16], kh[0], kh[1]);
                    mma_fp16(s[2 * np + 1], qf[k16], kh[2], kh[3]);
                }
            }

            if (kt * 64 + 63 > qbg) {
                int r0 = qbg + r_lo, r1 = r0 + 8;
#pragma unroll
                for (int nt = 0; nt < 8; ++nt) {
                    int kc = kt * 64 + nt * 8 + cb;
                    if (kc > r0)     s[nt][0] = -1e30f;
                    if (kc + 1 > r0) s[nt][1] = -1e30f;
                    if (kc > r1)     s[nt][2] = -1e30f;
                    if (kc + 1 > r1) s[nt][3] = -1e30f;
                }
            }

            float mx0 = -1e30f, mx1 = -1e30f;
#pragma unroll
            for (int nt = 0; nt < 8; ++nt) {
                mx0 = fmaxf(mx0, fmaxf(s[nt][0], s[nt][1]));
                mx1 = fmaxf(mx1, fmaxf(s[nt][2], s[nt][3]));
            }
            mx0 = fmaxf(mx0, __shfl_xor_sync(0xffffffffu, mx0, 1));
            mx0 = fmaxf(mx0, __shfl_xor_sync(0xffffffffu, mx0, 2));
            mx1 = fmaxf(mx1, __shfl_xor_sync(0xffffffffu, mx1, 1));
            mx1 = fmaxf(mx1, __shfl_xor_sync(0xffffffffu, mx1, 2));
            float mn0 = fmaxf(m0, mx0), mn1 = fmaxf(m1, mx1);
            float fac0 = __expf(m0 - mn0), fac1 = __expf(m1 - mn1);
            m0 = mn0; m1 = mn1;

            float sum0 = 0.f, sum1 = 0.f;
#pragma unroll
            for (int nt = 0; nt < 8; ++nt) {
                s[nt][0] = __expf(s[nt][0] - mn0);
                s[nt][1] = __expf(s[nt][1] - mn0);
                s[nt][2] = __expf(s[nt][2] - mn1);
                s[nt][3] = __expf(s[nt][3] - mn1);
                sum0 += s[nt][0] + s[nt][1];
                sum1 += s[nt][2] + s[nt][3];
            }
            sum0 += __shfl_xor_sync(0xffffffffu, sum0, 1);
            sum0 += __shfl_xor_sync(0xffffffffu, sum0, 2);
            sum1 += __shfl_xor_sync(0xffffffffu, sum1, 1);
            sum1 += __shfl_xor_sync(0xffffffffu, sum1, 2);
            l0 = l0 * fac0 + sum0;
            l1 = l1 * fac1 + sum1;

#pragma unroll
            for (int nt = 0; nt < 8; ++nt) {
                o[nt][0] *= fac0; o[nt][1] *= fac0;
                o[nt][2] *= fac1; o[nt][3] *= fac1;
            }

            // --- O += P V : P single fp16 ---
#pragma unroll
            for (int kv = 0; kv < 4; ++kv) {
                uint32_t pa[4];
                pa[0] = pack_fp16(s[2 * kv][0],     s[2 * kv][1]);
                pa[1] = pack_fp16(s[2 * kv][2],     s[2 * kv][3]);
                pa[2] = pack_fp16(s[2 * kv + 1][0], s[2 * kv + 1][1]);
                pa[3] = pack_fp16(s[2 * kv + 1][2], s[2 * kv + 1][3]);
#pragma unroll
                for (int np = 0; np < 4; ++np) {
                    int krow = kv * 16 + (tq & 1) * 8 + ri;
                    int h = np * 16 + (tq >> 1) * 8;
                    uint32_t vh[4];
                    ldmatrix_x4_trans(vh, stb + 1 * ARR_B + krow * 144 + h * 2);
                    mma_fp16(o[2 * np],     pa, vh[0], vh[1]);
                    mma_fp16(o[2 * np + 1], pa, vh[2], vh[3]);
                }
            }
        }

        __syncthreads();
        if (kt + 2 <= kmax) {
            stage_tile(smb + (kt & 1) * STAGE_B, b, kt + 2, tid);
            CP_COMMIT();
        } else {
            CP_COMMIT();
        }
    }

    float inv0 = 1.0f / l0, inv1 = 1.0f / l1;
    size_t gr0 = ((size_t)b * Tn + qbg + r_lo) * Hn;
    size_t gr1 = gr0 + 8 * Hn;
#pragma unroll
    for (int nt = 0; nt < 8; ++nt) {
        int col = nt * 8 + cb;
        *(float2*)&out[gr0 + col] = make_float2(o[nt][0] * inv0, o[nt][1] * inv0);
        *(float2*)&out[gr1 + col] = make_float2(o[nt][2] * inv1, o[nt][3] * inv1);
    }
}

// ---------------------------------------------------------------------------
extern "C" void kernel_launch(void* const* d_in, const int* in_sizes, int n_in,
                              void* d_out, int out_size)
{
    const float* x  = (const float*)d_in[0];
    const float* Wk = (const float*)d_in[1];
    const float* Wq = (const float*)d_in[2];
    const float* Wv = (const float*)d_in[3];
    float* out = (float*)d_out;

    prep_w_kernel<<<(24 * 24 * 32 + 255) / 256, 256>>>(Wk, Wq, Wv);

    cudaFuncSetAttribute(proj_mma_kernel,
                         cudaFuncAttributeMaxDynamicSharedMemorySize, PROJ_SMEM);
    proj_mma_kernel<<<(Bn * Tn) / 128, 256, PROJ_SMEM>>>(x);

    cudaFuncSetAttribute(attn_mma_kernel,
                         cudaFuncAttributeMaxDynamicSharedMemorySize, ATTN_SMEM);
    attn_mma_kernel<<<dim3(Tn / 128, Bn), 256, ATTN_SMEM>>>(out);
}

// round 16
// speedup vs baseline: 1.0134x; 1.0134x over previous
#include <cuda_runtime.h>
#include <cuda_bf16.h>
#include <cuda_fp16.h>
#include <cstdint>

#define Bn 1024
#define Tn 256
#define Cn 384
#define Hn 64

// Q/K/V as fp16, packed 2 cols per uint32: idx = row*32 + col/2.
// Q is pre-scaled by 0.125 (exact, power of two).
__device__ __align__(16) uint32_t g_q16[Bn * Tn * 32];
__device__ __align__(16) uint32_t g_k16[Bn * Tn * 32];
__device__ __align__(16) uint32_t g_v16[Bn * Tn * 32];

// Pre-packed fp16 B fragments for mma.sync.m16n8k16 (row.col)
__device__ __align__(16) uint2 g_bfrag[24 * 24 * 32];

// ---------------------------------------------------------------------------
__device__ __forceinline__ uint32_t smem_u32(const void* p) {
    uint32_t a;
    asm("{ .reg .u64 t; cvta.to.shared.u64 t, %1; cvt.u32.u64 %0, t; }" : "=r"(a) : "l"(p));
    return a;
}
__device__ __forceinline__ uint32_t pack_fp16(float a, float b) {
    uint32_t lo = __half_as_ushort(__float2half_rn(a));
    uint32_t hi = __half_as_ushort(__float2half_rn(b));
    return lo | (hi << 16);
}
__device__ __forceinline__ void mma_fp16(float* c, const uint32_t* a,
                                         uint32_t b0, uint32_t b1) {
    asm volatile(
        "mma.sync.aligned.m16n8k16.row.col.f32.f16.f16.f32 "
        "{%0,%1,%2,%3}, {%4,%5,%6,%7}, {%8,%9}, {%0,%1,%2,%3};"
        : "+f"(c[0]), "+f"(c[1]), "+f"(c[2]), "+f"(c[3])
        : "r"(a[0]), "r"(a[1]), "r"(a[2]), "r"(a[3]), "r"(b0), "r"(b1));
}
__device__ __forceinline__ void ldmatrix_x4(uint32_t* r, uint32_t addr) {
    asm volatile(
        "ldmatrix.sync.aligned.m8n8.x4.shared.b16 {%0,%1,%2,%3}, [%4];"
        : "=r"(r[0]), "=r"(r[1]), "=r"(r[2]), "=r"(r[3]) : "r"(addr));
}
__device__ __forceinline__ void ldmatrix_x4_trans(uint32_t* r, uint32_t addr) {
    asm volatile(
        "ldmatrix.sync.aligned.m8n8.x4.trans.shared.b16 {%0,%1,%2,%3}, [%4];"
        : "=r"(r[0]), "=r"(r[1]), "=r"(r[2]), "=r"(r[3]) : "r"(addr));
}
#define CP_ASYNC16(dst, src) \
    asm volatile("cp.async.cg.shared.global [%0], [%1], 16;" :: "r"(dst), "l"(src))
#define CP_COMMIT() asm volatile("cp.async.commit_group;" ::: "memory")
#define CP_WAIT(n)  asm volatile("cp.async.wait_group %0;" :: "n"(n) : "memory")

// ---------------------------------------------------------------------------
// Weight prep: fp16 W fragments in mma.sync register layout.
// ---------------------------------------------------------------------------
__global__ void prep_w_kernel(const float* __restrict__ Wk,
                              const float* __restrict__ Wq,
                              const float* __restrict__ Wv) {
    int idx = blockIdx.x * 256 + threadIdx.x;
    if (idx >= 24 * 24 * 32) return;
    int lane = idx & 31;
    int nt = (idx >> 5) % 24;
    int kt = (idx >> 5) / 24;

    int n = nt * 8 + (lane >> 2);
    int k0 = kt * 16 + (lane & 3) * 2;
    const float* W = (n < 64) ? Wq : (n < 128) ? Wk : Wv;
    int nc = n & 63;

    uint2 f;
    f.x = pack_fp16(W[(k0 + 0) * Hn + nc], W[(k0 + 1) * Hn + nc]);
    f.y = pack_fp16(W[(k0 + 8) * Hn + nc], W[(k0 + 9) * Hn + nc]);
    g_bfrag[idx] = f;
}

// ---------------------------------------------------------------------------
// Projection GEMM: single-product fp16, one sync per k-chunk.
// Block tile M=128, N=192; 8 warps (4 x M, 2 x N). 12 k-chunks of 32.
// ---------------------------------------------------------------------------
#define SB_OFF_U8 20480
#define PROJ_SMEM (20480 + 2 * 12288)

__global__ __launch_bounds__(256) void proj_mma_kernel(const float* __restrict__ x) {
    extern __shared__ __align__(16) char psm[];
    uint32_t* sA = (uint32_t*)psm;                 // [st*2560 + row*20 + col]
    uint2*    sB = (uint2*)(psm + SB_OFF_U8);      // [st*1536 + frag]

    const int tid = threadIdx.x;
    const int wid = tid >> 5;
    const int lane = tid & 31;
    const int row0 = blockIdx.x * 128;

    const int wm = (wid & 3) * 32;
    const int nw = wid >> 2;

    const int xr = tid >> 1;
    const int xc = (tid & 1) * 16;
    const float* xrow = x + (size_t)(row0 + xr) * Cn + xc;
    const char* gB = (const char*)g_bfrag;

#pragma unroll
    for (int j = 0; j < 3; ++j)
        CP_ASYNC16(smem_u32((char*)sB + (tid + j * 256) * 16),
                   gB + (tid + j * 256) * 16);
    CP_COMMIT();

    float4 v[4];
#pragma unroll
    for (int j = 0; j < 4; ++j) v[j] = __ldg((const float4*)xrow + j);
    {
        const int base = xr * 20 + xc / 2;
#pragma unroll
        for (int j = 0; j < 4; ++j) {
            sA[base + 2 * j + 0] = pack_fp16(v[j].x, v[j].y);
            sA[base + 2 * j + 1] = pack_fp16(v[j].z, v[j].w);
        }
    }

    float acc[2][12][4];
#pragma unroll
    for (int mt = 0; mt < 2; ++mt)
#pragma unroll
        for (int nt = 0; nt < 12; ++nt)
#pragma unroll
            for (int e = 0; e < 4; ++e) acc[mt][nt][e] = 0.f;

    const int lrow = lane & 15;
    const int lk8 = (lane >> 4) * 8;

    for (int c = 0; c < 12; ++c) {
        const int st = c & 1;

        if (c < 11) {
#pragma unroll
            for (int j = 0; j < 3; ++j)
                CP_ASYNC16(smem_u32((char*)sB + (st ^ 1) * 12288 + (tid + j * 256) * 16),
                           gB + (c + 1) * 12288 + (tid + j * 256) * 16);
            CP_COMMIT();
            const float* nx = xrow + (c + 1) * 32;
#pragma unroll
            for (int j = 0; j < 4; ++j) v[j] = __ldg((const float4*)nx + j);
        }
        if (c < 11) { CP_WAIT(1); } else { CP_WAIT(0); }
        __syncthreads();   // B_c arrived + A_c visible; prior readers of st done

        const uint32_t aBase = smem_u32(&sA[st * 2560]);

#pragma unroll
        for (int kt = 0; kt < 2; ++kt) {
            uint32_t af[2][4];
#pragma unroll
            for (int mt = 0; mt < 2; ++mt) {
                uint32_t off = (uint32_t)((wm + mt * 16 + lrow) * 80 +
                                          (kt * 16 + lk8) * 2);
                ldmatrix_x4(af[mt], aBase + off);
            }
            const uint2* bp = sB + (st * 1536 + ((kt * 24 + nw * 12) * 32 + lane));
#pragma unroll
            for (int nt = 0; nt < 12; ++nt) {
                uint2 bf = bp[nt * 32];
#pragma unroll
                for (int mt = 0; mt < 2; ++mt)
                    mma_fp16(acc[mt][nt], af[mt], bf.x, bf.y);
            }
        }

        // Restage A for chunk c+1 into the other stage. No barrier needed:
        // chunk c-1's readers of sA[st^1] completed before this chunk's sync,
        // and chunk c+1's readers are guarded by its own sync.
        if (c < 11) {
            const int base = (st ^ 1) * 2560 + xr * 20 + xc / 2;
#pragma unroll
            for (int j = 0; j < 4; ++j) {
                sA[base + 2 * j + 0] = pack_fp16(v[j].x, v[j].y);
                sA[base + 2 * j + 1] = pack_fp16(v[j].z, v[j].w);
            }
        }
    }

    // --- Epilogue: Q (pre-scaled), K, V all fp16 packed ---
#pragma unroll
    for (int mt = 0; mt < 2; ++mt) {
#pragma unroll
        for (int nt = 0; nt < 12; ++nt) {
            int n = nw * 96 + nt * 8 + (lane & 3) * 2;
            size_t r0g = (size_t)(row0 + wm + mt * 16 + (lane >> 2));
            float v0 = acc[mt][nt][0], v1 = acc[mt][nt][1];
            float v2 = acc[mt][nt][2], v3 = acc[mt][nt][3];
            uint32_t* dst;
            float sc;
            if (n < 64)      { dst = g_q16; sc = 0.125f; }
            else if (n < 128){ dst = g_k16; sc = 1.0f; }
            else             { dst = g_v16; sc = 1.0f; }
            int col2 = (n & 63) >> 1;
            dst[r0g * 32 + col2]       = pack_fp16(v0 * sc, v1 * sc);
            dst[(r0g + 8) * 32 + col2] = pack_fp16(v2 * sc, v3 * sc);
        }
    }
}

// ---------------------------------------------------------------------------
// Flash-attention: single-product fp16 throughout. Q pre-rounded fp16 from
// proj; P rounded to fp16. 128 q-rows per block (8 warps x 16 rows), K/V
// staged via cp.async, double-buffered.
// ---------------------------------------------------------------------------
#define ARR_B   9216
#define STAGE_B (2 * ARR_B)
#define ATTN_SMEM (2 * STAGE_B)

__device__ __forceinline__ void stage_tile(uint32_t dst, int b, int kt, int tid) {
    size_t base_byte = (((size_t)b * Tn + kt * 64) * 64) * 2;
    const char* pk = (const char*)g_k16 + base_byte;
    const char* pv = (const char*)g_v16 + base_byte;
#pragma unroll
    for (int i = 0; i < 2; ++i) {
        int g = tid * 2 + i;
        uint32_t doff = (uint32_t)((g >> 3) * 144 + (g & 7) * 16);
        CP_ASYNC16(dst + 0 * ARR_B + doff, pk + g * 16);
        CP_ASYNC16(dst + 1 * ARR_B + doff, pv + g * 16);
    }
}

__global__ __launch_bounds__(256) void attn_mma_kernel(float* __restrict__ out)
{
    extern __shared__ __align__(16) char tsm[];
    const uint32_t smb = smem_u32(tsm);

    const int tid = threadIdx.x;
    const int wid = tid >> 5;
    const int lane = tid & 31;
    const int qt = blockIdx.x;
    const int b = blockIdx.y;
    const int qb = wid * 16;
    const int qbg = qt * 128 + qb;
    const int kmax = qt * 2 + 1;
    const int ri = lane & 7;
    const int tq = lane >> 3;
    const int r_lo = lane >> 2;
    const int cb = (lane & 3) * 2;

    stage_tile(smb, b, 0, tid);            CP_COMMIT();
    stage_tile(smb + STAGE_B, b, 1, tid);  CP_COMMIT();

    // --- Q A-fragments: direct LDG of pre-scaled, pre-rounded fp16 pairs ---
    uint32_t qf[4][4];
    {
        const uint32_t* qp = g_q16 + ((size_t)b * Tn + qbg + r_lo) * 32;
#pragma unroll
        for (int k16 = 0; k16 < 4; ++k16) {
            int c2 = (k16 * 16 + cb) >> 1;
            qf[k16][0] = __ldg(qp + c2);
            qf[k16][1] = __ldg(qp + 8 * 32 + c2);
            qf[k16][2] = __ldg(qp + c2 + 4);
            qf[k16][3] = __ldg(qp + 8 * 32 + c2 + 4);
        }
    }

    float o[8][4];
#pragma unroll
    for (int nt = 0; nt < 8; ++nt)
#pragma unroll
        for (int e = 0; e < 4; ++e) o[nt][e] = 0.f;
    float m0 = -1e30f, m1 = -1e30f, l0 = 0.f, l1 = 0.f;

    for (int kt = 0; kt <= kmax; ++kt) {
        CP_WAIT(1);
        __syncthreads();

        const uint32_t stb = smb + (kt & 1) * STAGE_B;
        const bool active = (kt * 64) <= (qbg + 15);

        if (active) {
            // --- S = Q K^T : single-product fp16 ---
            float s[8][4];
#pragma unroll
            for (int nt = 0; nt < 8; ++nt)
#pragma unroll
                for (int e = 0; e < 4; ++e) s[nt][e] = 0.f;

#pragma unroll
            for (int k16 = 0; k16 < 4; ++k16) {
#pragma unroll
                for (int np = 0; np < 4; ++np) {
                    int krow = np * 16 + (tq >> 1) * 8 + ri;
                    int h = k16 * 16 + (tq & 1) * 8;
                    uint32_t kh[4];
                    ldmatrix_x4(kh, stb + 0 * ARR_B + krow * 144 + h * 2);
                    mma_fp16(s[2 * np],     qf[k16], kh[0], kh[1]);
                    mma_fp16(s[2 * np + 1], qf[k16], kh[2], kh[3]);
                }
            }

            if (kt * 64 + 63 > qbg) {
                int r0 = qbg + r_lo, r1 = r0 + 8;
#pragma unroll
                for (int nt = 0; nt < 8; ++nt) {
                    int kc = kt * 64 + nt * 8 + cb;
                    if (kc > r0)     s[nt][0] = -1e30f;
                    if (kc + 1 > r0) s[nt][1] = -1e30f;
                    if (kc > r1)     s[nt][2] = -1e30f;
                    if (kc + 1 > r1) s[nt][3] = -1e30f;
                }
            }

            float mx0 = -1e30f, mx1 = -1e30f;
#pragma unroll
            for (int nt = 0; nt < 8; ++nt) {
                mx0 = fmaxf(mx0, fmaxf(s[nt][0], s[nt][1]));
                mx1 = fmaxf(mx1, fmaxf(s[nt][2], s[nt][3]));
            }
            mx0 = fmaxf(mx0, __shfl_xor_sync(0xffffffffu, mx0, 1));
            mx0 = fmaxf(mx0, __shfl_xor_sync(0xffffffffu, mx0, 2));
            mx1 = fmaxf(mx1, __shfl_xor_sync(0xffffffffu, mx1, 1));
            mx1 = fmaxf(mx1, __shfl_xor_sync(0xffffffffu, mx1, 2));
            float mn0 = fmaxf(m0, mx0), mn1 = fmaxf(m1, mx1);
            float fac0 = __expf(m0 - mn0), fac1 = __expf(m1 - mn1);
            m0 = mn0; m1 = mn1;

            float sum0 = 0.f, sum1 = 0.f;
#pragma unroll
            for (int nt = 0; nt < 8; ++nt) {
                s[nt][0] = __expf(s[nt][0] - mn0);
                s[nt][1] = __expf(s[nt][1] - mn0);
                s[nt][2] = __expf(s[nt][2] - mn1);
                s[nt][3] = __expf(s[nt][3] - mn1);
                sum0 += s[nt][0] + s[nt][1];
                sum1 += s[nt][2] + s[nt][3];
            }
            sum0 += __shfl_xor_sync(0xffffffffu, sum0, 1);
            sum0 += __shfl_xor_sync(0xffffffffu, sum0, 2);
            sum1 += __shfl_xor_sync(0xffffffffu, sum1, 1);
            sum1 += __shfl_xor_sync(0xffffffffu, sum1, 2);
            l0 = l0 * fac0 + sum0;
            l1 = l1 * fac1 + sum1;

#pragma unroll
            for (int nt = 0; nt < 8; ++nt) {
                o[nt][0] *= fac0; o[nt][1] *= fac0;
                o[nt][2] *= fac1; o[nt][3] *= fac1;
            }

            // --- O += P V : P single fp16 ---
#pragma unroll
            for (int kv = 0; kv < 4; ++kv) {
                uint32_t pa[4];
                pa[0] = pack_fp16(s[2 * kv][0],     s[2 * kv][1]);
                pa[1] = pack_fp16(s[2 * kv][2],     s[2 * kv][3]);
                pa[2] = pack_fp16(s[2 * kv + 1][0], s[2 * kv + 1][1]);
                pa[3] = pack_fp16(s[2 * kv + 1][2], s[2 * kv + 1][3]);
#pragma unroll
                for (int np = 0; np < 4; ++np) {
                    int krow = kv * 16 + (tq & 1) * 8 + ri;
                    int h = np * 16 + (tq >> 1) * 8;
                    uint32_t vh[4];
                    ldmatrix_x4_trans(vh, stb + 1 * ARR_B + krow * 144 + h * 2);
                    mma_fp16(o[2 * np],     pa, vh[0], vh[1]);
                    mma_fp16(o[2 * np + 1], pa, vh[2], vh[3]);
                }
            }
        }

        __syncthreads();
        if (kt + 2 <= kmax) {
            stage_tile(smb + (kt & 1) * STAGE_B, b, kt + 2, tid);
            CP_COMMIT();
        } else {
            CP_COMMIT();
        }
    }

    float inv0 = 1.0f / l0, inv1 = 1.0f / l1;
    size_t gr0 = ((size_t)b * Tn + qbg + r_lo) * Hn;
    size_t gr1 = gr0 + 8 * Hn;
#pragma unroll
    for (int nt = 0; nt < 8; ++nt) {
        int col = nt * 8 + cb;
        *(float2*)&out[gr0 + col] = make_float2(o[nt][0] * inv0, o[nt][1] * inv0);
        *(float2*)&out[gr1 + col] = make_float2(o[nt][2] * inv1, o[nt][3] * inv1);
    }
}

// ---------------------------------------------------------------------------
extern "C" void kernel_launch(void* const* d_in, const int* in_sizes, int n_in,
                              void* d_out, int out_size)
{
    const float* x  = (const float*)d_in[0];
    const float* Wk = (const float*)d_in[1];
    const float* Wq = (const float*)d_in[2];
    const float* Wv = (const float*)d_in[3];
    float* out = (float*)d_out;

    prep_w_kernel<<<(24 * 24 * 32 + 255) / 256, 256>>>(Wk, Wq, Wv);

    cudaFuncSetAttribute(proj_mma_kernel,
                         cudaFuncAttributeMaxDynamicSharedMemorySize, PROJ_SMEM);
    proj_mma_kernel<<<(Bn * Tn) / 128, 256, PROJ_SMEM>>>(x);

    cudaFuncSetAttribute(attn_mma_kernel,
                         cudaFuncAttributeMaxDynamicSharedMemorySize, ATTN_SMEM);
    attn_mma_kernel<<<dim3(Tn / 128, Bn), 256, ATTN_SMEM>>>(out);
}